// round 9
// baseline (speedup 1.0000x reference)
#include <cuda_runtime.h>
#include <cstdint>

// Problem dims
#define Bv 64
#define Lv 512
#define Iv 256
#define Hv 512

// Partition: CG column groups x RG batch groups, persistent blocks
#define CG 32
#define RG 4
#define NBLK (CG*RG)
#define CPB 16     // cols per block  (Hv/CG)
#define BPB 16     // batches per block (Bv/RG)
#define NT 256     // threads per block
#define KCH 256    // k-chunk staged in smem

// Global state buffers, layout [k][batch] (batch fastest) for coalescing
__device__ float g_h [Hv*Bv];
__device__ float g_m [Hv*Bv];
__device__ float g_k1[Hv*Bv];
__device__ float g_k2[Hv*Bv];
__device__ float g_k3[Hv*Bv];
__device__ float g_ho[Hv*Bv];
__device__ unsigned g_bar[RG*32];   // one counter per batch group, 128B apart

// ---- group barrier: 32 blocks of one batch group ------------------------
__device__ __forceinline__ void gbar(unsigned* ctr, unsigned target) {
    __syncthreads();
    if (threadIdx.x == 0) {
        __threadfence();
        atomicAdd(ctr, 1u);
        while (*(volatile unsigned*)ctr < target) { }
        __threadfence();
    }
    __syncthreads();
}

__device__ __forceinline__ float sigm(float v) { return 1.0f / (1.0f + expf(-v)); }

// ---- single-accumulator GEMV over k=Hv, input staged via loader ---------
template <typename F>
__device__ __forceinline__ float gemv_h(const float* __restrict__ wrow,
                                        float* __restrict__ s_in,
                                        int tx, int tid, F ldr) {
    float acc = 0.0f;
    #pragma unroll
    for (int k0 = 0; k0 < Hv; k0 += KCH) {
        __syncthreads();
        #pragma unroll
        for (int ii = 0; ii < (KCH*BPB)/NT; ii++) {
            int idx = tid + ii*NT;
            s_in[idx] = ldr(k0 + (idx >> 4), idx & 15);
        }
        __syncthreads();
        const float* wr = wrow + k0;
        #pragma unroll 8
        for (int j = 0; j < KCH; j++)
            acc = fmaf(wr[j], s_in[j*BPB + tx], acc);
    }
    return acc;
}

// ---- 3-accumulator GEMV (gates r,z,n share the staged input) ------------
template <int KD, bool KFAST, typename F>
__device__ __forceinline__ void gemv3(const float* __restrict__ w0,
                                      const float* __restrict__ w1,
                                      const float* __restrict__ w2,
                                      float* __restrict__ s_in,
                                      int tx, int tid, F ldr,
                                      float& a0, float& a1, float& a2) {
    #pragma unroll
    for (int k0 = 0; k0 < KD; k0 += KCH) {
        __syncthreads();
        #pragma unroll
        for (int ii = 0; ii < (KCH*BPB)/NT; ii++) {
            int idx = tid + ii*NT;
            int kk, bl;
            if (KFAST) { kk = idx % KCH; bl = idx / KCH; }   // k fast (coalesced x reads)
            else       { kk = idx >> 4;  bl = idx & 15;  }   // batch fast
            s_in[kk*BPB + bl] = ldr(k0 + kk, bl);
        }
        __syncthreads();
        #pragma unroll 4
        for (int j = 0; j < KCH; j++) {
            float v = s_in[j*BPB + tx];
            a0 = fmaf(w0[k0+j], v, a0);
            a1 = fmaf(w1[k0+j], v, a1);
            a2 = fmaf(w2[k0+j], v, a2);
        }
    }
}

__global__ void init_bar_kernel() {
    if (threadIdx.x < RG*32) g_bar[threadIdx.x] = 0;
}

__global__ void __launch_bounds__(NT, 1)
odegru_main(const float* __restrict__ x,     const float* __restrict__ tdel,
            const float* __restrict__ w_ih,  const float* __restrict__ w_hh,
            const float* __restrict__ b_ih,  const float* __restrict__ b_hh,
            const float* __restrict__ dw0,   const float* __restrict__ db0,
            const float* __restrict__ dw1,   const float* __restrict__ db1,
            const float* __restrict__ h0,    const int*   __restrict__ seq_lens,
            float* __restrict__ out) {
    extern __shared__ float smem[];
    float* s_dw0 = smem;                      // CPB*Hv
    float* s_dw1 = s_dw0 + CPB*Hv;            // CPB*Hv
    float* s_whh = s_dw1 + CPB*Hv;            // 3*CPB*Hv
    float* s_wih = s_whh + 3*CPB*Hv;          // 3*CPB*Iv
    float* s_in  = s_wih + 3*CPB*Iv;          // KCH*BPB
    float* s_td  = s_in + KCH*BPB;            // BPB
    float* s_act = s_td + BPB;                // BPB

    const int blk = blockIdx.x;
    const int cg  = blk & (CG-1);
    const int rg  = blk >> 5;                 // CG==32
    const int c0  = cg*CPB, b0 = rg*BPB;
    const int tid = threadIdx.x;
    const int tx  = tid & 15;                 // local batch
    const int ty  = tid >> 4;                 // local col
    const int c   = c0 + ty;
    const int b   = b0 + tx;

    // Persistent weight slices (rows contiguous in the source matrices)
    for (int i = tid; i < CPB*Hv; i += NT) {
        s_dw0[i] = dw0[c0*Hv + i];
        s_dw1[i] = dw1[c0*Hv + i];
    }
    #pragma unroll
    for (int g = 0; g < 3; g++) {
        for (int i = tid; i < CPB*Hv; i += NT)
            s_whh[g*CPB*Hv + i] = w_hh[(g*Hv + c0)*Hv + i];
        for (int i = tid; i < CPB*Iv; i += NT)
            s_wih[g*CPB*Iv + i] = w_ih[(g*Hv + c0)*Iv + i];
    }

    const float db0c = db0[c], db1c = db1[c];
    const float bhr = b_hh[c], bhz = b_hh[Hv+c], bhn = b_hh[2*Hv+c];
    const float bir = b_ih[c], biz = b_ih[Hv+c], bin_ = b_ih[2*Hv+c];
    const int   slen = seq_lens[b];

    // init hidden state
    g_h[c*Bv + b] = h0[c];

    unsigned* ctr = &g_bar[rg*32];
    unsigned nbar = 0;

    const float* wdw0 = s_dw0 + ty*Hv;
    const float* wdw1 = s_dw1 + ty*Hv;
    const float* whr  = s_whh + ty*Hv;
    const float* whz  = s_whh + (CPB  + ty)*Hv;
    const float* whn  = s_whh + (2*CPB+ ty)*Hv;
    const float* wir  = s_wih + ty*Iv;
    const float* wiz  = s_wih + (CPB  + ty)*Iv;
    const float* win  = s_wih + (2*CPB+ ty)*Iv;

    for (int t = 0; t < Lv; t++) {
        // publish previous h / init (group barrier), then set per-step td & mask
        gbar(ctr, (++nbar)*32);
        if (tid < BPB) {
            int bb = b0 + tid;
            float a = (t < seq_lens[bb]) ? 1.0f : 0.0f;
            s_act[tid] = a;
            s_td[tid]  = a * tdel[bb*Lv + t];
        }
        __syncthreads();
        const float tdv = s_td[tx];

        // ---- RK4 (3/8 rule), dt = 1 ----
        // S1: m = tanh(h @ dw0^T + db0)
        {
            float acc = gemv_h(wdw0, s_in, tx, tid,
                [&](int k, int bl){ return g_h[k*Bv + b0 + bl]; });
            g_m[c*Bv + b] = tanhf(acc + db0c);
        }
        gbar(ctr, (++nbar)*32);
        // S2: k1 = tanh(m @ dw1^T + db1) * td
        float k1v;
        {
            float acc = gemv_h(wdw1, s_in, tx, tid,
                [&](int k, int bl){ return g_m[k*Bv + b0 + bl]; });
            k1v = tanhf(acc + db1c) * tdv;
            g_k1[c*Bv + b] = k1v;
        }
        gbar(ctr, (++nbar)*32);
        // S3: m = tanh((h + k1/3) @ dw0^T + db0)
        {
            float acc = gemv_h(wdw0, s_in, tx, tid,
                [&](int k, int bl){ int i = k*Bv + b0 + bl;
                    return g_h[i] + (1.0f/3.0f)*g_k1[i]; });
            g_m[c*Bv + b] = tanhf(acc + db0c);
        }
        gbar(ctr, (++nbar)*32);
        // S4: k2
        float k2v;
        {
            float acc = gemv_h(wdw1, s_in, tx, tid,
                [&](int k, int bl){ return g_m[k*Bv + b0 + bl]; });
            k2v = tanhf(acc + db1c) * tdv;
            g_k2[c*Bv + b] = k2v;
        }
        gbar(ctr, (++nbar)*32);
        // S5: m = tanh((h + k2 - k1/3) @ dw0^T + db0)
        {
            float acc = gemv_h(wdw0, s_in, tx, tid,
                [&](int k, int bl){ int i = k*Bv + b0 + bl;
                    return g_h[i] + g_k2[i] - (1.0f/3.0f)*g_k1[i]; });
            g_m[c*Bv + b] = tanhf(acc + db0c);
        }
        gbar(ctr, (++nbar)*32);
        // S6: k3
        float k3v;
        {
            float acc = gemv_h(wdw1, s_in, tx, tid,
                [&](int k, int bl){ return g_m[k*Bv + b0 + bl]; });
            k3v = tanhf(acc + db1c) * tdv;
            g_k3[c*Bv + b] = k3v;
        }
        gbar(ctr, (++nbar)*32);
        // S7: m = tanh((h + k1 - k2 + k3) @ dw0^T + db0)
        {
            float acc = gemv_h(wdw0, s_in, tx, tid,
                [&](int k, int bl){ int i = k*Bv + b0 + bl;
                    return g_h[i] + g_k1[i] - g_k2[i] + g_k3[i]; });
            g_m[c*Bv + b] = tanhf(acc + db0c);
        }
        gbar(ctr, (++nbar)*32);
        // S8: k4 ; h_ode = h + (k1 + 3(k2+k3) + k4)/8
        float hov;
        {
            float acc = gemv_h(wdw1, s_in, tx, tid,
                [&](int k, int bl){ return g_m[k*Bv + b0 + bl]; });
            float k4v = tanhf(acc + db1c) * tdv;
            float hv  = g_h[c*Bv + b];
            hov = hv + (k1v + 3.0f*(k2v + k3v) + k4v) * 0.125f;
            g_ho[c*Bv + b] = hov;
        }
        gbar(ctr, (++nbar)*32);
        // S9: GRU cell — gh = h_ode @ w_hh^T, gi = x_t @ w_ih^T, gates, h_new
        {
            float ar = 0.f, az = 0.f, an = 0.f;
            gemv3<Hv, false>(whr, whz, whn, s_in, tx, tid,
                [&](int k, int bl){ return g_ho[k*Bv + b0 + bl]; },
                ar, az, an);
            float xr = 0.f, xz = 0.f, xn = 0.f;
            gemv3<Iv, true>(wir, wiz, win, s_in, tx, tid,
                [&](int k, int bl){
                    return s_act[bl] * x[(b0 + bl)*(Lv*Iv) + t*Iv + k]; },
                xr, xz, xn);
            float r = sigm((xr + bir) + (ar + bhr));
            float z = sigm((xz + biz) + (az + bhz));
            float n = tanhf((xn + bin_) + r * (an + bhn));
            float hn = (1.0f - z) * n + z * hov;
            g_h[c*Bv + b] = hn;
            out[b*(Lv*Hv) + t*Hv + c] = hn;
            if (t == slen - 1)
                out[Bv*Lv*Hv + b*Hv + c] = hn;
        }
        // next loop-top gbar publishes g_h for the following step
    }
}

extern "C" void kernel_launch(void* const* d_in, const int* in_sizes, int n_in,
                              void* d_out, int out_size) {
    const float* x     = (const float*)d_in[0];
    const float* tdel  = (const float*)d_in[1];
    const float* w_ih  = (const float*)d_in[2];
    const float* w_hh  = (const float*)d_in[3];
    const float* b_ih  = (const float*)d_in[4];
    const float* b_hh  = (const float*)d_in[5];
    const float* dw0   = (const float*)d_in[6];
    const float* db0   = (const float*)d_in[7];
    const float* dw1   = (const float*)d_in[8];
    const float* db1   = (const float*)d_in[9];
    const float* h0    = (const float*)d_in[10];
    const int*   seq   = (const int*)d_in[11];
    float* out = (float*)d_out;

    // smem: weights (53248 f) + s_in (KCH*BPB) + td/act (32 f)
    size_t smem_bytes = (size_t)(CPB*Hv*2 + 3*CPB*Hv + 3*CPB*Iv + KCH*BPB + 2*BPB) * sizeof(float);
    cudaFuncSetAttribute(odegru_main, cudaFuncAttributeMaxDynamicSharedMemorySize,
                         (int)smem_bytes);

    init_bar_kernel<<<1, 128>>>();
    odegru_main<<<NBLK, NT, smem_bytes>>>(x, tdel, w_ih, w_hh, b_ih, b_hh,
                                          dw0, db0, dw1, db1, h0, seq, out);
}